// round 1
// baseline (speedup 1.0000x reference)
#include <cuda_runtime.h>
#include <math.h>

// ---------------- problem constants ----------------
// x: (4, 192, 256, 256) fp32, WS=8, shift=4, NHEADS=4, HD=48, nW=4096, T=64
#define LDX   193                      // padded row stride for 64x192 token tiles
#define OFF_X 0                        // w0 / w1 (64 x 192, stride LDX)  12352 f
#define OFF_O 12352                    // o concat / final out buffer     12352 f
#define OFF_S 24704                    // scratch union                   16512 f
#define OFF_Q (OFF_S)                  //   q   64x48 stride 49 (3136 f)
#define OFF_KT (OFF_S + 3136)          //   k^T 48x64 stride 65 (3120 f)
#define OFF_V (OFF_S + 6256)           //   v   64x48 stride 49 (3136 f)
#define OFF_P (OFF_S + 9392)           //   scores 64x64 stride 65 (4160 f)
#define OFF_H (OFF_S)                  //   LN2 output 64x192 stride LDX (12352 f)
#define OFF_G (OFF_S + 12352)          //   gelu tile 64x64 stride 65 (4160 f)
#define OFF_W 41216                    // weight staging tile 16x192 (3072 f)
#define SMEM_FLOATS 44288
#define SMEM_BYTES (SMEM_FLOATS * 4)

__global__ __launch_bounds__(256, 1)
void swin_block_kernel(const float* __restrict__ x,
                       const float* __restrict__ g1,  const float* __restrict__ b1,
                       const float* __restrict__ wqkv,const float* __restrict__ bqkv,
                       const float* __restrict__ wo,  const float* __restrict__ bo,
                       const float* __restrict__ g2,  const float* __restrict__ b2,
                       const float* __restrict__ wm1, const float* __restrict__ bm1,
                       const float* __restrict__ wm2, const float* __restrict__ bm2,
                       float* __restrict__ out)
{
    extern __shared__ float sm[];
    const int tid = threadIdx.x;
    const int wi  = blockIdx.x;
    const int b   = wi >> 10;          // image
    const int hb  = (wi >> 5) & 31;    // window row
    const int wb  = wi & 31;           // window col

    // ---------------- phase 0: gather window (shift folded into address) ----------------
    for (int idx = tid; idx < 64 * 192; idx += 256) {
        const int c  = idx >> 6;
        const int t  = idx & 63;
        const int ty = t >> 3, tx = t & 7;
        const int sh = (hb * 8 + ty + 4) & 255;   // roll(-4): rolled[i] = x[(i+4)%256]
        const int sw = (wb * 8 + tx + 4) & 255;
        sm[OFF_X + t * LDX + c] =
            x[(((size_t)(b * 192 + c)) << 16) + (sh << 8) + sw];
    }
    __syncthreads();

    // ---------------- LN1 (4 threads per token) ----------------
    {
        const int t = tid >> 2, qd = tid & 3;
        float s = 0.f, s2 = 0.f;
        #pragma unroll
        for (int j = 0; j < 48; j++) {
            float v = sm[OFF_X + t * LDX + qd * 48 + j];
            s += v; s2 += v * v;
        }
        s  += __shfl_xor_sync(0xffffffffu, s, 1);
        s2 += __shfl_xor_sync(0xffffffffu, s2, 1);
        s  += __shfl_xor_sync(0xffffffffu, s, 2);
        s2 += __shfl_xor_sync(0xffffffffu, s2, 2);
        const float mean = s * (1.f / 192.f);
        const float var  = s2 * (1.f / 192.f) - mean * mean;
        const float rstd = rsqrtf(var + 1e-5f);
        #pragma unroll
        for (int j = 0; j < 48; j++) {
            const int c = qd * 48 + j;
            float v = sm[OFF_X + t * LDX + c];
            sm[OFF_X + t * LDX + c] = (v - mean) * rstd * g1[c] + b1[c];
        }
    }
    __syncthreads();

    const int rg = tid >> 4;     // 0..15 row group (4 rows each)
    const int cg = tid & 15;     // 0..15 col group
    const int r0 = rg * 4;

    // ---------------- attention, one head at a time ----------------
    for (int h = 0; h < 4; h++) {
        // ---- qkv GEMM: (64x192) @ (192x144) -> q|k|v slabs of this head ----
        {
            float acc[4][9];
            #pragma unroll
            for (int i = 0; i < 4; i++)
                #pragma unroll
                for (int j = 0; j < 9; j++) acc[i][j] = 0.f;
            const int c0 = cg * 9;
            for (int k0 = 0; k0 < 192; k0 += 16) {
                for (int l = tid; l < 16 * 144; l += 256) {
                    const int kk = l / 144, j = l - kk * 144;
                    const int p = j / 48, jj = j - p * 48;
                    sm[OFF_W + l] = wqkv[(size_t)(k0 + kk) * 576 + p * 192 + h * 48 + jj];
                }
                __syncthreads();
                #pragma unroll 4
                for (int kk = 0; kk < 16; kk++) {
                    float a[4];
                    #pragma unroll
                    for (int i = 0; i < 4; i++) a[i] = sm[OFF_X + (r0 + i) * LDX + k0 + kk];
                    #pragma unroll
                    for (int j = 0; j < 9; j++) {
                        const float w = sm[OFF_W + kk * 144 + c0 + j];
                        #pragma unroll
                        for (int i = 0; i < 4; i++) acc[i][j] = fmaf(a[i], w, acc[i][j]);
                    }
                }
                __syncthreads();
            }
            // scatter with bias into q / k^T / v slabs
            #pragma unroll
            for (int j = 0; j < 9; j++) {
                const int cc = c0 + j;
                const int p = cc / 48, jj = cc - p * 48;
                const float bias = bqkv[p * 192 + h * 48 + jj];
                #pragma unroll
                for (int i = 0; i < 4; i++) {
                    const int r = r0 + i;
                    const float v = acc[i][j] + bias;
                    if (p == 0)      sm[OFF_Q  + r * 49 + jj] = v;
                    else if (p == 1) sm[OFF_KT + jj * 65 + r] = v;
                    else             sm[OFF_V  + r * 49 + jj] = v;
                }
            }
        }
        __syncthreads();

        // ---- scores: Q (64x48) @ K^T (48x64), scaled ----
        {
            float sc[4][4];
            #pragma unroll
            for (int i = 0; i < 4; i++)
                #pragma unroll
                for (int j = 0; j < 4; j++) sc[i][j] = 0.f;
            const int c0s = cg * 4;
            #pragma unroll 8
            for (int k = 0; k < 48; k++) {
                float a[4];
                #pragma unroll
                for (int i = 0; i < 4; i++) a[i] = sm[OFF_Q + (r0 + i) * 49 + k];
                #pragma unroll
                for (int j = 0; j < 4; j++) {
                    const float kb = sm[OFF_KT + k * 65 + c0s + j];
                    #pragma unroll
                    for (int i = 0; i < 4; i++) sc[i][j] = fmaf(a[i], kb, sc[i][j]);
                }
            }
            const float scale = 0.14433756729740643f;   // 1/sqrt(48)
            #pragma unroll
            for (int i = 0; i < 4; i++)
                #pragma unroll
                for (int j = 0; j < 4; j++)
                    sm[OFF_P + (r0 + i) * 65 + c0s + j] = sc[i][j] * scale;
        }
        __syncthreads();

        // ---- softmax over 64 keys (4 threads per row) ----
        {
            const int t = tid >> 2, qd = tid & 3;
            float m = -1e30f;
            #pragma unroll
            for (int j = 0; j < 16; j++)
                m = fmaxf(m, sm[OFF_P + t * 65 + qd * 16 + j]);
            m = fmaxf(m, __shfl_xor_sync(0xffffffffu, m, 1));
            m = fmaxf(m, __shfl_xor_sync(0xffffffffu, m, 2));
            float s = 0.f;
            #pragma unroll
            for (int j = 0; j < 16; j++) {
                const float e = __expf(sm[OFF_P + t * 65 + qd * 16 + j] - m);
                sm[OFF_P + t * 65 + qd * 16 + j] = e;
                s += e;
            }
            s += __shfl_xor_sync(0xffffffffu, s, 1);
            s += __shfl_xor_sync(0xffffffffu, s, 2);
            const float inv = 1.f / s;
            #pragma unroll
            for (int j = 0; j < 16; j++)
                sm[OFF_P + t * 65 + qd * 16 + j] *= inv;
        }
        __syncthreads();

        // ---- AV: P (64x64) @ V (64x48) -> o slab [*, h*48 .. h*48+48) ----
        {
            float ao[4][3];
            #pragma unroll
            for (int i = 0; i < 4; i++)
                #pragma unroll
                for (int j = 0; j < 3; j++) ao[i][j] = 0.f;
            const int c0v = cg * 3;
            #pragma unroll 8
            for (int k = 0; k < 64; k++) {
                float a[4];
                #pragma unroll
                for (int i = 0; i < 4; i++) a[i] = sm[OFF_P + (r0 + i) * 65 + k];
                #pragma unroll
                for (int j = 0; j < 3; j++) {
                    const float v = sm[OFF_V + k * 49 + c0v + j];
                    #pragma unroll
                    for (int i = 0; i < 4; i++) ao[i][j] = fmaf(a[i], v, ao[i][j]);
                }
            }
            #pragma unroll
            for (int i = 0; i < 4; i++)
                #pragma unroll
                for (int j = 0; j < 3; j++)
                    sm[OFF_O + (r0 + i) * LDX + h * 48 + c0v + j] = ao[i][j];
        }
        __syncthreads();
    }

    // ---------------- o-proj + residual: w1 = w0 + o @ Wo + bo (in place in sX) ----------------
    {
        float acc[4][12];
        #pragma unroll
        for (int i = 0; i < 4; i++)
            #pragma unroll
            for (int j = 0; j < 12; j++) acc[i][j] = 0.f;
        const int c0 = cg * 12;
        for (int k0 = 0; k0 < 192; k0 += 16) {
            for (int l = tid; l < 3072; l += 256) {
                const int kk = l / 192, j = l - kk * 192;
                sm[OFF_W + l] = wo[(size_t)(k0 + kk) * 192 + j];
            }
            __syncthreads();
            #pragma unroll 4
            for (int kk = 0; kk < 16; kk++) {
                float a[4];
                #pragma unroll
                for (int i = 0; i < 4; i++) a[i] = sm[OFF_O + (r0 + i) * LDX + k0 + kk];
                #pragma unroll
                for (int j = 0; j < 12; j++) {
                    const float w = sm[OFF_W + kk * 192 + c0 + j];
                    #pragma unroll
                    for (int i = 0; i < 4; i++) acc[i][j] = fmaf(a[i], w, acc[i][j]);
                }
            }
            __syncthreads();
        }
        #pragma unroll
        for (int j = 0; j < 12; j++) {
            const int c = c0 + j;
            const float bb = bo[c];
            #pragma unroll
            for (int i = 0; i < 4; i++)
                sm[OFF_X + (r0 + i) * LDX + c] += acc[i][j] + bb;
        }
    }
    __syncthreads();

    // ---------------- LN2: sX (w1) -> sH ----------------
    {
        const int t = tid >> 2, qd = tid & 3;
        float s = 0.f, s2 = 0.f;
        #pragma unroll
        for (int j = 0; j < 48; j++) {
            float v = sm[OFF_X + t * LDX + qd * 48 + j];
            s += v; s2 += v * v;
        }
        s  += __shfl_xor_sync(0xffffffffu, s, 1);
        s2 += __shfl_xor_sync(0xffffffffu, s2, 1);
        s  += __shfl_xor_sync(0xffffffffu, s, 2);
        s2 += __shfl_xor_sync(0xffffffffu, s2, 2);
        const float mean = s * (1.f / 192.f);
        const float var  = s2 * (1.f / 192.f) - mean * mean;
        const float rstd = rsqrtf(var + 1e-5f);
        #pragma unroll
        for (int j = 0; j < 48; j++) {
            const int c = qd * 48 + j;
            const float v = sm[OFF_X + t * LDX + c];
            sm[OFF_H + t * LDX + c] = (v - mean) * rstd * g2[c] + b2[c];
        }
    }
    __syncthreads();

    // ---------------- MLP: out = w1 + gelu(sH @ W1 + b1) @ W2 + b2, j-tiled by 64 ----------------
    {
        float accm[4][12];
        #pragma unroll
        for (int i = 0; i < 4; i++)
            #pragma unroll
            for (int j = 0; j < 12; j++) accm[i][j] = 0.f;
        const int c0  = cg * 12;
        const int c0g = cg * 4;
        for (int jt = 0; jt < 12; jt++) {
            // ---- G = sH @ W1[:, jt*64 .. jt*64+64) ----
            float g[4][4];
            #pragma unroll
            for (int i = 0; i < 4; i++)
                #pragma unroll
                for (int j = 0; j < 4; j++) g[i][j] = 0.f;
            for (int k0 = 0; k0 < 192; k0 += 16) {
                for (int l = tid; l < 1024; l += 256) {
                    const int kk = l >> 6, j = l & 63;
                    sm[OFF_W + l] = wm1[(size_t)(k0 + kk) * 768 + jt * 64 + j];
                }
                __syncthreads();
                #pragma unroll 4
                for (int kk = 0; kk < 16; kk++) {
                    float a[4];
                    #pragma unroll
                    for (int i = 0; i < 4; i++) a[i] = sm[OFF_H + (r0 + i) * LDX + k0 + kk];
                    #pragma unroll
                    for (int j = 0; j < 4; j++) {
                        const float w = sm[OFF_W + kk * 64 + c0g + j];
                        #pragma unroll
                        for (int i = 0; i < 4; i++) g[i][j] = fmaf(a[i], w, g[i][j]);
                    }
                }
                __syncthreads();
            }
            // ---- exact GELU into sG ----
            #pragma unroll
            for (int j = 0; j < 4; j++) {
                const int cc = c0g + j;
                const float bb = bm1[jt * 64 + cc];
                #pragma unroll
                for (int i = 0; i < 4; i++) {
                    const float v = g[i][j] + bb;
                    sm[OFF_G + (r0 + i) * 65 + cc] =
                        0.5f * v * (1.f + erff(v * 0.70710678118654752f));
                }
            }
            __syncthreads();
            // ---- accm += sG @ W2[jt*64 .. jt*64+64, :] ----
            for (int k0 = 0; k0 < 64; k0 += 16) {
                for (int l = tid; l < 3072; l += 256) {
                    const int kk = l / 192, j = l - kk * 192;
                    sm[OFF_W + l] = wm2[(size_t)(jt * 64 + k0 + kk) * 192 + j];
                }
                __syncthreads();
                #pragma unroll 4
                for (int kk = 0; kk < 16; kk++) {
                    float a[4];
                    #pragma unroll
                    for (int i = 0; i < 4; i++) a[i] = sm[OFF_G + (r0 + i) * 65 + k0 + kk];
                    #pragma unroll
                    for (int j = 0; j < 12; j++) {
                        const float w = sm[OFF_W + kk * 192 + c0 + j];
                        #pragma unroll
                        for (int i = 0; i < 4; i++) accm[i][j] = fmaf(a[i], w, accm[i][j]);
                    }
                }
                __syncthreads();
            }
        }
        // ---- residual + stage c-major for coalesced store ----
        #pragma unroll
        for (int j = 0; j < 12; j++) {
            const int c = c0 + j;
            const float bb = bm2[c];
            #pragma unroll
            for (int i = 0; i < 4; i++) {
                const float v = accm[i][j] + bb + sm[OFF_X + (r0 + i) * LDX + c];
                sm[OFF_O + c * 64 + (r0 + i)] = v;
            }
        }
    }
    __syncthreads();

    // ---------------- scatter back (inverse roll folded into address) ----------------
    for (int idx = tid; idx < 64 * 192; idx += 256) {
        const int c  = idx >> 6;
        const int t  = idx & 63;
        const int ty = t >> 3, tx = t & 7;
        const int sh = (hb * 8 + ty + 4) & 255;
        const int sw = (wb * 8 + tx + 4) & 255;
        out[(((size_t)(b * 192 + c)) << 16) + (sh << 8) + sw] = sm[OFF_O + idx];
    }
}

extern "C" void kernel_launch(void* const* d_in, const int* in_sizes, int n_in,
                              void* d_out, int out_size)
{
    (void)in_sizes; (void)n_in; (void)out_size;
    const float* x    = (const float*)d_in[0];
    const float* g1   = (const float*)d_in[1];
    const float* b1   = (const float*)d_in[2];
    const float* wqkv = (const float*)d_in[3];
    const float* bqkv = (const float*)d_in[4];
    const float* wo   = (const float*)d_in[5];
    const float* bo   = (const float*)d_in[6];
    const float* g2   = (const float*)d_in[7];
    const float* b2   = (const float*)d_in[8];
    const float* wm1  = (const float*)d_in[9];
    const float* bm1  = (const float*)d_in[10];
    const float* wm2  = (const float*)d_in[11];
    const float* bm2  = (const float*)d_in[12];
    float* out = (float*)d_out;

    cudaFuncSetAttribute(swin_block_kernel,
                         cudaFuncAttributeMaxDynamicSharedMemorySize, SMEM_BYTES);
    swin_block_kernel<<<4096, 256, SMEM_BYTES>>>(
        x, g1, b1, wqkv, bqkv, wo, bo, g2, b2, wm1, bm1, wm2, bm2, out);
}